// round 15
// baseline (speedup 1.0000x reference)
#include <cuda_runtime.h>
#include <math.h>

#define TSTEPS 512
#define BATCH  64
#define DIN    256
#define HID    512
#define DOUT   256
#define G4H    2048
#define NBLK   128
#define NCH    4      // batch chains
#define BCH    16     // batches per chain
#define NTHR   576    // 16 recur warps + 2 co-processor warps

typedef unsigned long long ull;

// ---------------- scratch ----------------
__device__ float d_Genc[(size_t)TSTEPS * G4H * BATCH];    // [t][gate*512+u][b]
__device__ float d_Gdec[(size_t)TSTEPS * G4H * BATCH];
__device__ float d_hq[NCH][2][256 * BCH * 2];             // [chain][parity][kpair][b16][2]
__device__ float d_cbuf[HID * BATCH];                     // [u][b]
__device__ float d_hs[(size_t)TSTEPS * HID * BATCH];      // [t][u][b]
__device__ float d_logits[(size_t)TSTEPS * BATCH * DOUT]; // [t][b][n]
__device__ unsigned d_cntg[NCH * 8 * 32];                 // group counters (stride-32 lines)
__device__ unsigned d_cntr[NCH * 32];                     // root counters
__device__ volatile int d_epoch[NCH * 32];                // broadcast line per chain

// ---------------- helpers ----------------
__device__ __forceinline__ void fma2(ull& a, ull x, ull y) {
    asm("fma.rn.f32x2 %0, %1, %2, %3;" : "=l"(a) : "l"(x), "l"(y), "l"(a));
}
__device__ __forceinline__ void fadd2(ull& a, ull x) {
    asm("add.rn.f32x2 %0, %1, %2;" : "=l"(a) : "l"(a), "l"(x));
}
__device__ __forceinline__ ull pack2(float lo, float hi) {
    ull r; asm("mov.b64 %0, {%1, %2};" : "=l"(r) : "f"(lo), "f"(hi)); return r;
}
__device__ __forceinline__ float sum2(ull v) {
    float lo, hi; asm("mov.b64 {%0, %1}, %2;" : "=f"(lo), "=f"(hi) : "l"(v));
    return lo + hi;
}
__device__ __forceinline__ ull ldcg64(const ull* p) {
    ull v; asm volatile("ld.global.cg.u64 %0, [%1];" : "=l"(v) : "l"(p)); return v;
}
__device__ __forceinline__ int ld_acq(const volatile int* p) {
    int v; asm volatile("ld.acquire.gpu.global.s32 %0, [%1];" : "=r"(v) : "l"(p) : "memory");
    return v;
}
__device__ __forceinline__ void st_rel(volatile int* p, int v) {
    asm volatile("st.release.gpu.global.s32 [%0], %1;" :: "l"(p), "r"(v) : "memory");
}
__device__ __forceinline__ void barx(int id) {
    asm volatile("bar.sync %0, 128;" :: "r"(id) : "memory");
}
__device__ __forceinline__ void barco() {
    asm volatile("bar.sync 5, 64;" ::: "memory");
}
__device__ __forceinline__ float fsig(float x) {
    return __fdividef(1.0f, 1.0f + __expf(-x));
}
__device__ __forceinline__ float ftanh(float x) {
    float e = __expf(2.0f * x);                 // inf-safe
    return 1.0f - __fdividef(2.0f, e + 1.0f);
}

// ---------------- init: pack initial h/c per chain, reset sync state ----------------
__global__ __launch_bounds__(256) void init_state(const float* __restrict__ h0,
                                                  const float* __restrict__ c0) {
    int i = blockIdx.x * blockDim.x + threadIdx.x;
    if (i < NCH * 8) d_cntg[i * 32] = 0u;
    if (i < NCH) { d_cntr[i * 32] = 0u; d_epoch[i * 32] = 0; }
    if (i >= HID * BATCH) return;
    int b = i >> 9;                 // h0 layout [1][B][H]
    int u = i & 511;
    int q = b >> 4, b16 = b & 15;
    d_hq[q][0][((u >> 1) * BCH + b16) * 2 + (u & 1)] = h0[i];
    d_cbuf[u * BATCH + b] = c0[i];
}

// ---------------- unified register-blocked GEMM (R9-proven; used for enc-proj) ----------------
__global__ __launch_bounds__(256, 2) void gemm_kernel(
    const float* __restrict__ X, const float* __restrict__ W,
    const float* __restrict__ bias, float* __restrict__ Out,
    int Ntot, int K, int kchunks, int dec_shift, int x_kb, int out_bn) {
    __shared__ ull Wt[16 * 130];
    __shared__ ull Xt[16 * 66];

    int t  = blockIdx.y;
    int n0 = blockIdx.x * 128;
    int tid = threadIdx.x;
    int tx = tid & 15, ty = tid >> 4;

    ull acc[8][4];
#pragma unroll
    for (int i = 0; i < 8; i++)
#pragma unroll
        for (int j = 0; j < 4; j++) acc[i][j] = 0ull;

    for (int ch = 0; ch < kchunks; ch++) {
        for (int idx = tid; idx < 2048; idx += 256) {
            int kk = idx & 15, n = idx >> 4;
            Wt[kk * 130 + n] = *(const ull*)(W + (size_t)(n0 + n) * K + ch * 32 + kk * 2);
        }
        if (x_kb) {
            for (int idx = tid; idx < 1024; idx += 256) {
                int b = idx & 63, kk = idx >> 6;
                int kg = ch * 32 + kk * 2;
                Xt[kk * 66 + b] = pack2(X[((size_t)t * K + kg) * 64 + b],
                                        X[((size_t)t * K + kg + 1) * 64 + b]);
            }
        } else {
            bool zero = (dec_shift && t == 0);
            int trow = t - dec_shift;
            for (int idx = tid; idx < 1024; idx += 256) {
                int kk = idx & 15, b = idx >> 4;
                Xt[kk * 66 + b] = zero ? 0ull
                    : *(const ull*)(X + ((size_t)trow * 64 + b) * K + ch * 32 + kk * 2);
            }
        }
        __syncthreads();
#pragma unroll
        for (int kk = 0; kk < 16; kk++) {
            ulonglong2 xv0 = *(const ulonglong2*)&Xt[kk * 66 + tx * 4];
            ulonglong2 xv1 = *(const ulonglong2*)&Xt[kk * 66 + tx * 4 + 2];
            ull xs0 = xv0.x, xs1 = xv0.y, xs2 = xv1.x, xs3 = xv1.y;
#pragma unroll
            for (int q = 0; q < 4; q++) {
                ulonglong2 wv = *(const ulonglong2*)&Wt[kk * 130 + ty * 8 + 2 * q];
                fma2(acc[2 * q][0], wv.x, xs0);
                fma2(acc[2 * q][1], wv.x, xs1);
                fma2(acc[2 * q][2], wv.x, xs2);
                fma2(acc[2 * q][3], wv.x, xs3);
                fma2(acc[2 * q + 1][0], wv.y, xs0);
                fma2(acc[2 * q + 1][1], wv.y, xs1);
                fma2(acc[2 * q + 1][2], wv.y, xs2);
                fma2(acc[2 * q + 1][3], wv.y, xs3);
            }
        }
        __syncthreads();
    }

    if (out_bn) {
        float bb[8];
#pragma unroll
        for (int i = 0; i < 8; i++) bb[i] = bias[n0 + ty * 8 + i];
#pragma unroll
        for (int j = 0; j < 4; j++) {
            int b = tx * 4 + j;
            float v[8];
#pragma unroll
            for (int i = 0; i < 8; i++) v[i] = sum2(acc[i][j]) + bb[i];
            float* op = Out + ((size_t)t * 64 + b) * Ntot + n0 + ty * 8;
            *(float4*)op       = make_float4(v[0], v[1], v[2], v[3]);
            *(float4*)(op + 4) = make_float4(v[4], v[5], v[6], v[7]);
        }
    } else {
#pragma unroll
        for (int i = 0; i < 8; i++) {
            int n = n0 + ty * 8 + i;
            float bb = bias[n];
            float4 o = make_float4(sum2(acc[i][0]) + bb, sum2(acc[i][1]) + bb,
                                   sum2(acc[i][2]) + bb, sum2(acc[i][3]) + bb);
            *(float4*)(Out + ((size_t)t * Ntot + n) * 64 + tx * 4) = o;
        }
    }
}

// ---------------- co-processor tile compute: 64 threads, 32n x 32b, 16 kpairs ----------------
__device__ __forceinline__ void co_compute(const ull* Wt2, const ull* Xt2,
                                           ull acc[4][4], int tx, int ty) {
#pragma unroll
    for (int kk = 0; kk < 16; kk++) {
        ulonglong2 xa = *(const ulonglong2*)&Xt2[kk * 34 + tx * 4];
        ulonglong2 xb = *(const ulonglong2*)&Xt2[kk * 34 + tx * 4 + 2];
        ulonglong2 wa = *(const ulonglong2*)&Wt2[kk * 34 + ty * 4];
        ulonglong2 wb = *(const ulonglong2*)&Wt2[kk * 34 + ty * 4 + 2];
        fma2(acc[0][0], wa.x, xa.x); fma2(acc[0][1], wa.x, xa.y);
        fma2(acc[0][2], wa.x, xb.x); fma2(acc[0][3], wa.x, xb.y);
        fma2(acc[1][0], wa.y, xa.x); fma2(acc[1][1], wa.y, xa.y);
        fma2(acc[1][2], wa.y, xb.x); fma2(acc[1][3], wa.y, xb.y);
        fma2(acc[2][0], wb.x, xa.x); fma2(acc[2][1], wb.x, xa.y);
        fma2(acc[2][2], wb.x, xb.x); fma2(acc[2][3], wb.x, xb.y);
        fma2(acc[3][0], wb.y, xa.x); fma2(acc[3][1], wb.y, xa.y);
        fma2(acc[3][2], wb.y, xb.x); fma2(acc[3][3], wb.y, xb.y);
    }
}

// ---------------- persistent recurrent LSTM + co-processor warps ----------------
// Warps 0-15: R14 recurrence (4 chains, tree-atomic arrival) — unchanged.
// Warps 16-17 (64 threads): co-processor.
//   which==0 (encoder): compute ALL of d_Gdec (decoder input projection) — no deps.
//   which==1 (decoder): compute FC logits tiles, gated on chain epochs (hs[t] ready).
__global__ __launch_bounds__(NTHR) void recur_kernel(const float* __restrict__ Whh,
                                                     int which, int sbase,
                                                     const float* __restrict__ Xco,
                                                     const float* __restrict__ Wco,
                                                     const float* __restrict__ bco) {
    extern __shared__ ull sm[];
    ull* ws  = sm;              // [kpair][16 rows]   4096 ull = 32 KB
    ull* red = sm + 4096;       // per chain: [(row*16+b16)*9 + slot], 2304 ull each
    ull* Wt2 = sm + 13312;      // co: [16 kk][32n + pad2] = 544 ull
    ull* Xt2 = sm + 13856;      // co: [16 kk][32b + pad2] = 544 ull

    int tid = threadIdx.x;
    int bid = blockIdx.x;
    int u0 = bid * 4;

    // weights: [kpair][row], row = gate*4 + unit (all 576 threads help)
    for (int idx = tid; idx < 4096; idx += NTHR) {
        int kp = idx >> 4, r = idx & 15;
        int g = r >> 2, uu = r & 3;
        ws[idx] = *(const ull*)(Whh + ((size_t)(g * HID + u0 + uu)) * HID + kp * 2);
    }
    __syncthreads();

    // ================= co-processor path =================
    if (tid >= 512) {
        int ctid = tid - 512;               // 0..63
        int tx = ctid & 7, ty = ctid >> 3;  // tx -> 4 b, ty -> 4 n
        if (which == 0) {
            // dec input projection: Gdec[t][n][b] = dec_in[t] @ Wco^T + bco
            // tiles: 512 t x 64 n-tiles(32) x 2 b-halves = 65536
            for (int tt = bid; tt < 65536; tt += NBLK) {
                int t = tt >> 7, r = tt & 127;
                int n0 = (r >> 1) * 32, bh = r & 1;
                ull acc[4][4];
#pragma unroll
                for (int i = 0; i < 4; i++)
#pragma unroll
                    for (int j = 0; j < 4; j++) acc[i][j] = 0ull;
                for (int ch = 0; ch < 8; ch++) {            // K = 256
                    for (int idx = ctid; idx < 512; idx += 64) {
                        int kk = idx & 15, n = idx >> 4;
                        Wt2[kk * 34 + n] =
                            *(const ull*)(Wco + (size_t)(n0 + n) * DOUT + ch * 32 + kk * 2);
                    }
                    if (t == 0) {
                        for (int idx = ctid; idx < 512; idx += 64) {
                            int kk = idx & 15, b = idx >> 4;
                            Xt2[kk * 34 + b] = 0ull;
                        }
                    } else {
                        for (int idx = ctid; idx < 512; idx += 64) {
                            int kk = idx & 15, b = idx >> 4;
                            Xt2[kk * 34 + b] = *(const ull*)(Xco +
                                ((size_t)(t - 1) * 64 + bh * 32 + b) * DOUT + ch * 32 + kk * 2);
                        }
                    }
                    barco();
                    co_compute(Wt2, Xt2, acc, tx, ty);
                    barco();
                }
#pragma unroll
                for (int i = 0; i < 4; i++) {
                    int n = n0 + ty * 4 + i;
                    float bbv = bco[n];
                    float4 o = make_float4(sum2(acc[i][0]) + bbv, sum2(acc[i][1]) + bbv,
                                           sum2(acc[i][2]) + bbv, sum2(acc[i][3]) + bbv);
                    *(float4*)(d_Gdec + ((size_t)t * G4H + n) * 64 + bh * 32 + tx * 4) = o;
                }
            }
        } else {
            // FC: logits[t][b][n] = hs[t] @ Wco^T + bco, gated on hs[t] completion
            // tiles: 512 t x 8 n-tiles(32) x 2 b-halves = 8192 (t-major -> monotonic gate)
            for (int tt = bid; tt < 8192; tt += NBLK) {
                int t = tt >> 4, r = tt & 15;
                int n0 = (r >> 1) * 32, bh = r & 1;
                int tgt = TSTEPS + t + 1;
                if (ctid == 0) {
                    while (min(min(ld_acq(&d_epoch[0]),  ld_acq(&d_epoch[32])),
                               min(ld_acq(&d_epoch[64]), ld_acq(&d_epoch[96]))) < tgt) { }
                }
                barco();
                // per-thread acquire (epoch monotonic: single read suffices post-bar)
                while (min(min(ld_acq(&d_epoch[0]),  ld_acq(&d_epoch[32])),
                           min(ld_acq(&d_epoch[64]), ld_acq(&d_epoch[96]))) < tgt) { }
                ull acc[4][4];
#pragma unroll
                for (int i = 0; i < 4; i++)
#pragma unroll
                    for (int j = 0; j < 4; j++) acc[i][j] = 0ull;
                for (int ch = 0; ch < 16; ch++) {           // K = 512
                    for (int idx = ctid; idx < 512; idx += 64) {
                        int kk = idx & 15, n = idx >> 4;
                        Wt2[kk * 34 + n] =
                            *(const ull*)(Wco + (size_t)(n0 + n) * HID + ch * 32 + kk * 2);
                    }
                    for (int idx = ctid; idx < 512; idx += 64) {
                        int kk = idx & 15, b = idx >> 4;
                        int kg = ch * 32 + kk * 2;
                        Xt2[kk * 34 + b] =
                            pack2(d_hs[((size_t)t * HID + kg) * 64 + bh * 32 + b],
                                  d_hs[((size_t)t * HID + kg + 1) * 64 + bh * 32 + b]);
                    }
                    barco();
                    co_compute(Wt2, Xt2, acc, tx, ty);
                    barco();
                }
#pragma unroll
                for (int j = 0; j < 4; j++) {
                    int b = bh * 32 + tx * 4 + j;
                    int n = n0 + ty * 4;
                    float4 o = make_float4(sum2(acc[0][j]) + bco[n],
                                           sum2(acc[1][j]) + bco[n + 1],
                                           sum2(acc[2][j]) + bco[n + 2],
                                           sum2(acc[3][j]) + bco[n + 3]);
                    *(float4*)(d_logits + ((size_t)t * 64 + b) * DOUT + n) = o;
                }
            }
        }
        return;
    }

    // ================= recurrence path (identical to R14) =================
    const float* __restrict__ G = which ? d_Gdec : d_Genc;
    int w = tid >> 5, l = tid & 31;
    int q = w >> 2;                 // chain
    int wi = w & 3;                 // warp-in-chain (also SMSP)
    int b16 = l & 15, kh = l >> 4;  // FMA lane mapping

    int e = wi * 32 + l;
    int ul = (e >> 4) & 3, eb16 = e & 15;
    int u = u0 + ul;
    float c = (wi < 2) ? d_cbuf[u * BATCH + q * BCH + eb16] : 0.0f;

    ull* rq = red + q * 2304;
    int kbase = wi * 64 + kh * 32;
    const int barid = 1 + q;
    volatile int* epoch = &d_epoch[q * 32];
    unsigned* cg = &d_cntg[(q * 8 + (bid >> 4)) * 32];
    unsigned* cr = &d_cntr[q * 32];

    for (int t = 0; t < TSTEPS; t++) {
        int s = sbase + t;

        // prefetch precomputed gate inputs (LDGs overlap the wait)
        float pi = 0.f, pf = 0.f, pg = 0.f, po = 0.f;
        if (wi < 2) {
            size_t gb = ((size_t)t * G4H + u) * BATCH + q * BCH + eb16;
            pi = G[gb];
            pf = G[gb + (size_t)512 * 64];
            pg = G[gb + (size_t)1024 * 64];
            po = G[gb + (size_t)1536 * 64];
        }

        // wait for h_s (single poller per chain per block)
        if (wi == 0 && l == 0) { while (ld_acq(epoch) < s) { } }
        barx(barid);

        const ull* hsrc = (const ull*)d_hq[q][s & 1] + b16;
        ull acc[16];
#pragma unroll
        for (int r = 0; r < 16; r++) acc[r] = 0ull;

        ull hg[2][8];
#pragma unroll
        for (int j = 0; j < 8; j++) hg[0][j] = ldcg64(hsrc + (size_t)(kbase + j) * BCH);
#pragma unroll
        for (int g4 = 0; g4 < 4; g4++) {
            int cur = g4 & 1, nxt = cur ^ 1;
            if (g4 < 3) {
#pragma unroll
                for (int j = 0; j < 8; j++)
                    hg[nxt][j] = ldcg64(hsrc + (size_t)(kbase + (g4 + 1) * 8 + j) * BCH);
            }
#pragma unroll
            for (int j = 0; j < 8; j++) {
                const ulonglong2* wp = (const ulonglong2*)(ws + (size_t)(kbase + g4 * 8 + j) * 16);
                ull hv = hg[cur][j];
#pragma unroll
                for (int rp = 0; rp < 8; rp++) {
                    ulonglong2 wv = wp[rp];
                    fma2(acc[2 * rp],     wv.x, hv);
                    fma2(acc[2 * rp + 1], wv.y, hv);
                }
            }
        }
#pragma unroll
        for (int r = 0; r < 16; r++)
            rq[(size_t)(r * 16 + b16) * 9 + wi * 2 + kh] = acc[r];
        barx(barid);                        // partials ready; h_s reads done

        if (wi < 2) {
            float gate[4];
#pragma unroll
            for (int g = 0; g < 4; g++) {
                int r = g * 4 + ul;
                const ull* rp_ = rq + (size_t)(r * 16 + eb16) * 9;
                ull a0 = rp_[0]; fadd2(a0, rp_[1]); fadd2(a0, rp_[2]); fadd2(a0, rp_[3]);
                ull a1 = rp_[4]; fadd2(a1, rp_[5]); fadd2(a1, rp_[6]); fadd2(a1, rp_[7]);
                fadd2(a0, a1);
                gate[g] = sum2(a0);
            }
            float iv = fsig(gate[0] + pi);
            float fv = fsig(gate[1] + pf);
            float gv = ftanh(gate[2] + pg);
            float ov = fsig(gate[3] + po);
            c = fv * c + iv * gv;
            float h = ov * ftanh(c);

            d_hq[q][(s + 1) & 1][((u >> 1) * BCH + eb16) * 2 + (u & 1)] = h;
            if (which) d_hs[((size_t)t * HID + u) * BATCH + q * BCH + eb16] = h;
        }
        barx(barid);                        // h_{s+1} visible chain-wide

        // tree arrival: group counter (16 blocks) -> root (8 groups) -> epoch
        if (wi == 3 && l == 0) {
            __threadfence();
            unsigned og = atomicAdd(cg, 1u);
            if (og == 16u * (unsigned)(s + 1) - 1u) {
                unsigned orr = atomicAdd(cr, 1u);
                if (orr == 8u * (unsigned)(s + 1) - 1u) st_rel(epoch, s + 1);
            }
        }
    }
    if (wi < 2) d_cbuf[u * BATCH + q * BCH + eb16] = c;   // enc -> dec handoff
}

// ---------------- softmax over last dim (256), one warp per (t,b) row ----------------
__global__ __launch_bounds__(256) void softmax_kernel(float* __restrict__ out) {
    int row = blockIdx.x * 8 + (threadIdx.x >> 5);
    if (row >= TSTEPS * BATCH) return;
    int lane = threadIdx.x & 31;
    const float* lp = d_logits + (size_t)row * DOUT;
    float v[8];
    float m = -INFINITY;
#pragma unroll
    for (int i = 0; i < 8; i++) { v[i] = lp[lane + 32 * i]; m = fmaxf(m, v[i]); }
#pragma unroll
    for (int o = 16; o > 0; o >>= 1) m = fmaxf(m, __shfl_xor_sync(0xffffffffu, m, o));
    float s = 0.0f;
#pragma unroll
    for (int i = 0; i < 8; i++) { v[i] = expf(v[i] - m); s += v[i]; }
#pragma unroll
    for (int o = 16; o > 0; o >>= 1) s += __shfl_xor_sync(0xffffffffu, s, o);
    float inv = 1.0f / s;
    float* op = out + (size_t)row * DOUT;
#pragma unroll
    for (int i = 0; i < 8; i++) op[lane + 32 * i] = v[i] * inv;
}

// ---------------- launch ----------------
extern "C" void kernel_launch(void* const* d_in, const int* in_sizes, int n_in,
                              void* d_out, int out_size) {
    const float* x      = (const float*)d_in[0];
    const float* target = (const float*)d_in[1];
    const float* h0     = (const float*)d_in[2];
    const float* c0     = (const float*)d_in[3];
    const float* eWih   = (const float*)d_in[4];
    const float* eWhh   = (const float*)d_in[5];
    const float* eb     = (const float*)d_in[6];
    const float* dWih   = (const float*)d_in[7];
    const float* dWhh   = (const float*)d_in[8];
    const float* db     = (const float*)d_in[9];
    const float* fcW    = (const float*)d_in[10];
    const float* fcb    = (const float*)d_in[11];
    float* out = (float*)d_out;

    const int smem_recur = (4096 + NCH * 2304 + 2 * 544) * 8;   // 115200 B
    cudaFuncSetAttribute(recur_kernel, cudaFuncAttributeMaxDynamicSharedMemorySize, smem_recur);

    init_state<<<128, 256>>>(h0, c0);

    float* genc; cudaGetSymbolAddress((void**)&genc, d_Genc);

    // encoder input projection (standalone)
    gemm_kernel<<<dim3(16, TSTEPS), 256>>>(x, eWih, eb, genc, G4H, DIN, DIN / 32, 0, 0, 0);

    // encoder recurrence; co-warps compute dec input projection in its shadow
    recur_kernel<<<NBLK, NTHR, smem_recur>>>(eWhh, 0, 0, target, dWih, db);
    // decoder recurrence; co-warps compute FC logits gated on epoch progress
    recur_kernel<<<NBLK, NTHR, smem_recur>>>(dWhh, 1, TSTEPS, nullptr, fcW, fcb);

    softmax_kernel<<<(TSTEPS * BATCH + 7) / 8, 256>>>(out);
}